// round 2
// baseline (speedup 1.0000x reference)
#include <cuda_runtime.h>
#include <cuda_bf16.h>

#define NMAX 200000
#define HD 32
#define BN_EPS 1e-5f

// ---- scratch (no allocations allowed; __device__ globals) ----
__device__ int    g_deg[NMAX];
__device__ float  g_norm[NMAX];
__device__ float  g_stmp[NMAX];
__device__ float  g_s[NMAX];
__device__ float4 g_U[NMAX * 8];     // [N,32] node messages (t * norm[n]), float4-packed
__device__ float4 g_AGG[NMAX * 8];   // [N,32] scatter accumulator / z buffer
__device__ double g_stats[130];      // [0,1]=layer1 sum,sumsq ; [2..33]+[34..65]=L2 ; [66..97]+[98..129]=L3

// ---------------- degree count ----------------
__global__ void k_deg(const int* __restrict__ dst, int E) {
    int e = blockIdx.x * blockDim.x + threadIdx.x;
    if (e < E) atomicAdd(&g_deg[dst[e]], 1);
}

// ---------------- norm = rsqrt(deg+1) ----------------
__global__ void k_norm(int n) {
    int i = blockIdx.x * blockDim.x + threadIdx.x;
    if (i < n) g_norm[i] = rsqrtf((float)g_deg[i] + 1.0f);
}

// ---------------- layer-1 scalar scatter: stmp[dst] += x[src]*norm[src] ----------------
__global__ void k_scat1(const int* __restrict__ src, const int* __restrict__ dst,
                        const float* __restrict__ x, int E) {
    int e = blockIdx.x * blockDim.x + threadIdx.x;
    if (e < E) {
        int s = src[e], d = dst[e];
        atomicAdd(&g_stmp[d], x[s] * g_norm[s]);
    }
}

// ---------------- finalize s, reduce mean/var stats ----------------
__global__ void k_sfin(const float* __restrict__ x, int n) {
    double acc = 0.0, acc2 = 0.0;
    int stride = gridDim.x * blockDim.x;
    for (int i = blockIdx.x * blockDim.x + threadIdx.x; i < n; i += stride) {
        float nr = g_norm[i];
        float s  = nr * g_stmp[i] + x[i] * nr * nr;
        g_s[i] = s;
        acc  += (double)s;
        acc2 += (double)s * (double)s;
    }
    __shared__ double sh[256], sh2[256];
    sh[threadIdx.x] = acc; sh2[threadIdx.x] = acc2;
    __syncthreads();
    for (int o = 128; o > 0; o >>= 1) {
        if (threadIdx.x < o) { sh[threadIdx.x] += sh[threadIdx.x + o]; sh2[threadIdx.x] += sh2[threadIdx.x + o]; }
        __syncthreads();
    }
    if (threadIdx.x == 0) {
        atomicAdd(&g_stats[0], sh[0]);
        atomicAdd(&g_stats[1], sh2[0]);
    }
}

// ---------------- h1 = relu(bn1(s*W1)), t2 = h1 @ W2, U = t2*norm ----------------
__global__ void k_layer1(const float* __restrict__ W1, const float* __restrict__ g1,
                         const float* __restrict__ be1, const float* __restrict__ W2, int n) {
    __shared__ float sW[HD * HD];
    for (int i = threadIdx.x; i < HD * HD; i += blockDim.x) sW[i] = W2[i];
    __syncthreads();

    int lane = threadIdx.x & 31;
    int node = (blockIdx.x * blockDim.x + threadIdx.x) >> 5;
    if (node >= n) return;

    double mu = g_stats[0] / (double)n;
    double vr = g_stats[1] / (double)n - mu * mu;
    float mean_s = (float)mu;
    float var_s  = (float)vr;

    float w = W1[lane];
    float a = g1[lane] * w * rsqrtf(var_s * w * w + BN_EPS);
    float h = fmaxf(a * (g_s[node] - mean_s) + be1[lane], 0.0f);

    float t = 0.0f;
    #pragma unroll
    for (int k = 0; k < HD; k++) {
        float hk = __shfl_sync(0xffffffffu, h, k);
        t += hk * sW[k * HD + lane];
    }
    ((float*)g_U)[node * HD + lane] = t * g_norm[node];
}

// ---------------- 32-wide scatter: AGG[dst] += U[src]  (vector reds) ----------------
__global__ void k_scat(const int* __restrict__ src, const int* __restrict__ dst, int E) {
    int t = blockIdx.x * blockDim.x + threadIdx.x;
    int e = t >> 3, k = t & 7;
    if (e >= E) return;
    int s = src[e], d = dst[e];
    float4 v = g_U[s * 8 + k];
    float4* p = &g_AGG[d * 8 + k];
    asm volatile("red.global.add.v4.f32 [%0], {%1,%2,%3,%4};"
                 :: "l"(p), "f"(v.x), "f"(v.y), "f"(v.z), "f"(v.w) : "memory");
}

// ---------------- node epilogue: z = norm*(AGG+U)+b, store z in AGG, column stats ----------------
__global__ void k_post(const float* __restrict__ b, double* __restrict__ ss, double* __restrict__ sq, int n) {
    float bj = b[threadIdx.x & 31];
    double acc = 0.0, acc2 = 0.0;
    int stride = gridDim.x * blockDim.x;          // multiple of 32
    float* AGG = (float*)g_AGG;
    const float* U = (const float*)g_U;
    for (int i = blockIdx.x * blockDim.x + threadIdx.x; i < n * HD; i += stride) {
        int node = i >> 5;
        float z = g_norm[node] * (AGG[i] + U[i]) + bj;
        AGG[i] = z;
        acc  += (double)z;
        acc2 += (double)z * (double)z;
    }
    __shared__ double sh[256], sh2[256];
    sh[threadIdx.x] = acc; sh2[threadIdx.x] = acc2;
    __syncthreads();
    for (int o = 128; o >= 32; o >>= 1) {
        if (threadIdx.x < o) { sh[threadIdx.x] += sh[threadIdx.x + o]; sh2[threadIdx.x] += sh2[threadIdx.x + o]; }
        __syncthreads();
    }
    if (threadIdx.x < 32) {
        atomicAdd(&ss[threadIdx.x], sh[threadIdx.x]);
        atomicAdd(&sq[threadIdx.x], sh2[threadIdx.x]);
    }
}

// ---------------- h = relu(bn(z)), t = h @ Wn, U = t*norm ----------------
__global__ void k_mid(const float* __restrict__ g, const float* __restrict__ be,
                      const float* __restrict__ Wn,
                      const double* __restrict__ ss, const double* __restrict__ sq, int n) {
    __shared__ float sW[HD * HD];
    for (int i = threadIdx.x; i < HD * HD; i += blockDim.x) sW[i] = Wn[i];
    __syncthreads();

    int lane = threadIdx.x & 31;
    int node = (blockIdx.x * blockDim.x + threadIdx.x) >> 5;
    if (node >= n) return;

    double mu = ss[lane] / (double)n;
    float sd  = rsqrtf((float)(sq[lane] / (double)n - mu * mu) + BN_EPS);
    float mean = (float)mu;

    float z = ((float*)g_AGG)[node * HD + lane];
    float h = fmaxf(g[lane] * ((z - mean) * sd) + be[lane], 0.0f);

    float t = 0.0f;
    #pragma unroll
    for (int k = 0; k < HD; k++) {
        float hk = __shfl_sync(0xffffffffu, h, k);
        t += hk * sW[k * HD + lane];
    }
    ((float*)g_U)[node * HD + lane] = t * g_norm[node];
}

// ---------------- output: out[n] = relu(bn3(z)) . fcW + fcb ----------------
__global__ void k_out(const float* __restrict__ g, const float* __restrict__ be,
                      const float* __restrict__ fcW, const float* __restrict__ fcb,
                      const double* __restrict__ ss, const double* __restrict__ sq,
                      int n, float* __restrict__ out) {
    int lane = threadIdx.x & 31;
    int node = (blockIdx.x * blockDim.x + threadIdx.x) >> 5;
    if (node >= n) return;

    double mu = ss[lane] / (double)n;
    float sd  = rsqrtf((float)(sq[lane] / (double)n - mu * mu) + BN_EPS);
    float mean = (float)mu;

    float z = ((float*)g_AGG)[node * HD + lane];
    float h = fmaxf(g[lane] * ((z - mean) * sd) + be[lane], 0.0f);
    float v = h * fcW[lane];
    #pragma unroll
    for (int o = 16; o > 0; o >>= 1) v += __shfl_xor_sync(0xffffffffu, v, o);
    if (lane == 0) out[node] = v + fcb[0];
}

extern "C" void kernel_launch(void* const* d_in, const int* in_sizes, int n_in,
                              void* d_out, int out_size) {
    const float* x   = (const float*)d_in[0];
    const int*   ei  = (const int*)d_in[1];     // int32 (JAX x64 disabled downgrades int64)
    // d_in[2] = edge_attr (unused by reference)
    const float* W1  = (const float*)d_in[3];
    const float* g1  = (const float*)d_in[5];
    const float* be1 = (const float*)d_in[6];
    const float* W2  = (const float*)d_in[7];
    const float* b2  = (const float*)d_in[8];
    const float* g2  = (const float*)d_in[9];
    const float* be2 = (const float*)d_in[10];
    const float* W3  = (const float*)d_in[11];
    const float* b3  = (const float*)d_in[12];
    const float* g3  = (const float*)d_in[13];
    const float* be3 = (const float*)d_in[14];
    const float* fcW = (const float*)d_in[15];
    const float* fcb = (const float*)d_in[16];
    float* out = (float*)d_out;

    int n = in_sizes[0];
    int E = in_sizes[1] / 2;
    const int* src = ei;
    const int* dst = ei + E;

    void *pdeg, *pstmp, *pstats, *pagg;
    cudaGetSymbolAddress(&pdeg,   g_deg);
    cudaGetSymbolAddress(&pstmp,  g_stmp);
    cudaGetSymbolAddress(&pstats, g_stats);
    cudaGetSymbolAddress(&pagg,   g_AGG);
    double* stats = (double*)pstats;

    const int T = 256;
    int bE  = (E + T - 1) / T;
    int bN  = (n + T - 1) / T;
    int bNW = (n * HD + T - 1) / T;      // warp-per-node kernels
    int bS  = (E * 8 + T - 1) / T;       // vector scatter
    int bR  = 592;                       // grid-stride reduction kernels

    cudaMemsetAsync(pdeg,   0, (size_t)n * sizeof(int));
    cudaMemsetAsync(pstmp,  0, (size_t)n * sizeof(float));
    cudaMemsetAsync(pstats, 0, 130 * sizeof(double));

    // degrees -> norm
    k_deg<<<bE, T>>>(dst, E);
    k_norm<<<bN, T>>>(n);

    // layer 1 (scalar propagation)
    k_scat1<<<bE, T>>>(src, dst, x, E);
    k_sfin<<<bR, T>>>(x, n);

    // h1 -> t2*norm into U
    k_layer1<<<bNW, T>>>(W1, g1, be1, W2, n);

    // layer 2 aggregation
    cudaMemsetAsync(pagg, 0, (size_t)n * HD * sizeof(float));
    k_scat<<<bS, T>>>(src, dst, E);
    k_post<<<bR, T>>>(b2, stats + 2, stats + 34, n);

    // h2 -> t3*norm into U
    k_mid<<<bNW, T>>>(g2, be2, W3, stats + 2, stats + 34, n);

    // layer 3 aggregation
    cudaMemsetAsync(pagg, 0, (size_t)n * HD * sizeof(float));
    k_scat<<<bS, T>>>(src, dst, E);
    k_post<<<bR, T>>>(b3, stats + 66, stats + 98, n);

    // output
    k_out<<<bNW, T>>>(g3, be3, fcW, fcb, stats + 66, stats + 98, n, out);
}

// round 3
// speedup vs baseline: 1.0631x; 1.0631x over previous
#include <cuda_runtime.h>
#include <cuda_bf16.h>

#define NMAX 200000
#define EMAX 2500000
#define HD 32
#define BN_EPS 1e-5f

// ---- scratch (__device__ globals; no allocations allowed) ----
__device__ int    g_deg[NMAX];
__device__ int    g_off[NMAX];
__device__ int    g_cur[NMAX];
__device__ int    g_adj[EMAX];       // CSR: src ids grouped by dst
__device__ int    g_bsum[256];
__device__ int    g_boff[256];
__device__ float  g_norm[NMAX];
__device__ float  g_xn[NMAX];        // x * norm
__device__ float  g_s[NMAX];
__device__ float4 g_U[NMAX * 8];     // [N,32] messages t*norm
__device__ float4 g_Z[NMAX * 8];     // [N,32] pre-BN activations
__device__ double g_stats[130];      // [0,1]=L1 ; [2..65]=L2 ; [66..129]=L3

// ---------------- degree count ----------------
__global__ void k_deg(const int* __restrict__ dst, int E) {
    int e = blockIdx.x * blockDim.x + threadIdx.x;
    if (e < E) atomicAdd(&g_deg[dst[e]], 1);
}

// ---------------- scan stage A: per-1024-chunk sums ----------------
__global__ void k_scanA(int n) {
    int b = blockIdx.x, tid = threadIdx.x;
    int base = b * 1024 + tid * 4;
    int s = 0;
    #pragma unroll
    for (int i = 0; i < 4; i++) { int idx = base + i; if (idx < n) s += g_deg[idx]; }
    // warp reduce then block reduce
    for (int o = 16; o > 0; o >>= 1) s += __shfl_xor_sync(0xffffffffu, s, o);
    __shared__ int sh[8];
    if ((tid & 31) == 0) sh[tid >> 5] = s;
    __syncthreads();
    if (tid == 0) {
        int t = 0;
        #pragma unroll
        for (int k = 0; k < 8; k++) t += sh[k];
        g_bsum[b] = t;
    }
}

// ---------------- scan stage B: exclusive scan of chunk sums (1 block) ----------------
__global__ void k_scanB(int nb) {
    int tid = threadIdx.x;             // 256 threads
    __shared__ int sh[256];
    int v = (tid < nb) ? g_bsum[tid] : 0;
    sh[tid] = v;
    __syncthreads();
    for (int o = 1; o < 256; o <<= 1) {
        int t = (tid >= o) ? sh[tid - o] : 0;
        __syncthreads();
        sh[tid] += t;
        __syncthreads();
    }
    g_boff[tid] = sh[tid] - v;         // exclusive
}

// ---------------- scan stage C: element offsets + norm/xn ----------------
__global__ void k_scanC(const float* __restrict__ x, int n) {
    int b = blockIdx.x, tid = threadIdx.x;
    int lane = tid & 31, wid = tid >> 5;
    int base = b * 1024 + tid * 4;
    int d[4];
    #pragma unroll
    for (int i = 0; i < 4; i++) { int idx = base + i; d[i] = (idx < n) ? g_deg[idx] : 0; }
    int tsum = d[0] + d[1] + d[2] + d[3];
    // inclusive warp scan of tsum
    int v = tsum;
    for (int o = 1; o < 32; o <<= 1) {
        int t = __shfl_up_sync(0xffffffffu, v, o);
        if (lane >= o) v += t;
    }
    __shared__ int wsum[8], woff[8];
    if (lane == 31) wsum[wid] = v;
    __syncthreads();
    if (tid < 8) { int s = 0; for (int k = 0; k < tid; k++) s += wsum[k]; woff[tid] = s; }
    __syncthreads();
    int run = g_boff[b] + woff[wid] + (v - tsum);   // exclusive offset for this thread's first elem
    #pragma unroll
    for (int i = 0; i < 4; i++) {
        int idx = base + i;
        if (idx < n) {
            g_off[idx] = run;
            g_cur[idx] = run;
            float nr = rsqrtf((float)d[i] + 1.0f);
            g_norm[idx] = nr;
            g_xn[idx] = x[idx] * nr;
        }
        run += d[i];
    }
}

// ---------------- fill CSR ----------------
__global__ void k_fill(const int* __restrict__ src, const int* __restrict__ dst, int E) {
    int e = blockIdx.x * blockDim.x + threadIdx.x;
    if (e < E) {
        int pos = atomicAdd(&g_cur[dst[e]], 1);
        g_adj[pos] = src[e];
    }
}

// ---------------- layer-1 scalar gather + stats ----------------
__global__ void k_gscal(const float* __restrict__ x, int n) {
    int lane = threadIdx.x & 31, w = threadIdx.x >> 5;
    int gw = blockIdx.x * 8 + w, nw = gridDim.x * 8;
    double a = 0.0, a2 = 0.0;
    for (int node = gw; node < n; node += nw) {
        int beg = g_off[node], deg = g_deg[node];
        float acc = 0.0f;
        for (int j = lane; j < deg; j += 32) acc += g_xn[g_adj[beg + j]];
        for (int o = 16; o > 0; o >>= 1) acc += __shfl_xor_sync(0xffffffffu, acc, o);
        if (lane == 0) {
            float nr = g_norm[node];
            float s = nr * acc + x[node] * nr * nr;
            g_s[node] = s;
            a += (double)s;
            a2 += (double)s * (double)s;
        }
    }
    __shared__ double sh[256], sh2[256];
    sh[threadIdx.x] = a; sh2[threadIdx.x] = a2;
    __syncthreads();
    for (int o = 128; o > 0; o >>= 1) {
        if (threadIdx.x < o) { sh[threadIdx.x] += sh[threadIdx.x + o]; sh2[threadIdx.x] += sh2[threadIdx.x + o]; }
        __syncthreads();
    }
    if (threadIdx.x == 0) {
        atomicAdd(&g_stats[0], sh[0]);
        atomicAdd(&g_stats[1], sh2[0]);
    }
}

// ---------------- h1 = relu(bn1(s*W1)), U = (h1 @ W2)*norm ----------------
__global__ void k_layer1(const float* __restrict__ W1, const float* __restrict__ g1,
                         const float* __restrict__ be1, const float* __restrict__ W2, int n) {
    __shared__ float sW[HD * HD];
    for (int i = threadIdx.x; i < HD * HD; i += blockDim.x) sW[i] = W2[i];
    __syncthreads();
    int lane = threadIdx.x & 31;
    int node = (blockIdx.x * blockDim.x + threadIdx.x) >> 5;
    if (node >= n) return;
    double mu = g_stats[0] / (double)n;
    double vr = g_stats[1] / (double)n - mu * mu;
    float w = W1[lane];
    float a = g1[lane] * w * rsqrtf((float)vr * w * w + BN_EPS);
    float h = fmaxf(a * (g_s[node] - (float)mu) + be1[lane], 0.0f);
    float t = 0.0f;
    #pragma unroll
    for (int k = 0; k < HD; k++) {
        float hk = __shfl_sync(0xffffffffu, h, k);
        t += hk * sW[k * HD + lane];
    }
    ((float*)g_U)[node * HD + lane] = t * g_norm[node];
}

// ---------------- 32-wide gather: Z = norm*(sum U[adj] + U[self]) + b, + stats ----------------
__global__ void k_gath(const float* __restrict__ bvec, double* __restrict__ ss,
                       double* __restrict__ sq, int n) {
    int lane = threadIdx.x & 31, w = threadIdx.x >> 5;
    int gw = blockIdx.x * 8 + w, nw = gridDim.x * 8;
    float bj = bvec[lane];
    const float* U = (const float*)g_U;
    float* Z = (float*)g_Z;
    double a = 0.0, a2 = 0.0;
    for (int node = gw; node < n; node += nw) {
        int beg = g_off[node], deg = g_deg[node];
        float acc = 0.0f;
        int j = 0;
        for (; j + 4 <= deg; j += 4) {
            int s0 = g_adj[beg + j], s1 = g_adj[beg + j + 1];
            int s2 = g_adj[beg + j + 2], s3 = g_adj[beg + j + 3];
            float v0 = U[s0 * HD + lane], v1 = U[s1 * HD + lane];
            float v2 = U[s2 * HD + lane], v3 = U[s3 * HD + lane];
            acc += v0 + v1 + v2 + v3;
        }
        for (; j < deg; j++) acc += U[g_adj[beg + j] * HD + lane];
        float z = g_norm[node] * (acc + U[node * HD + lane]) + bj;
        Z[node * HD + lane] = z;
        a += (double)z;
        a2 += (double)z * (double)z;
    }
    __shared__ double sh[256], sh2[256];
    sh[threadIdx.x] = a; sh2[threadIdx.x] = a2;
    __syncthreads();
    if (threadIdx.x < 32) {
        double s = 0.0, s2 = 0.0;
        #pragma unroll
        for (int k = 0; k < 8; k++) { s += sh[k * 32 + threadIdx.x]; s2 += sh2[k * 32 + threadIdx.x]; }
        atomicAdd(&ss[threadIdx.x], s);
        atomicAdd(&sq[threadIdx.x], s2);
    }
}

// ---------------- h = relu(bn(Z)), U = (h @ Wn)*norm ----------------
__global__ void k_mid(const float* __restrict__ g, const float* __restrict__ be,
                      const float* __restrict__ Wn,
                      const double* __restrict__ ss, const double* __restrict__ sq, int n) {
    __shared__ float sW[HD * HD];
    for (int i = threadIdx.x; i < HD * HD; i += blockDim.x) sW[i] = Wn[i];
    __syncthreads();
    int lane = threadIdx.x & 31;
    int node = (blockIdx.x * blockDim.x + threadIdx.x) >> 5;
    if (node >= n) return;
    double mu = ss[lane] / (double)n;
    float sd = rsqrtf((float)(sq[lane] / (double)n - mu * mu) + BN_EPS);
    float z = ((float*)g_Z)[node * HD + lane];
    float h = fmaxf(g[lane] * ((z - (float)mu) * sd) + be[lane], 0.0f);
    float t = 0.0f;
    #pragma unroll
    for (int k = 0; k < HD; k++) {
        float hk = __shfl_sync(0xffffffffu, h, k);
        t += hk * sW[k * HD + lane];
    }
    ((float*)g_U)[node * HD + lane] = t * g_norm[node];
}

// ---------------- out = relu(bn3(Z)) . fcW + fcb ----------------
__global__ void k_out(const float* __restrict__ g, const float* __restrict__ be,
                      const float* __restrict__ fcW, const float* __restrict__ fcb,
                      const double* __restrict__ ss, const double* __restrict__ sq,
                      int n, float* __restrict__ out) {
    int lane = threadIdx.x & 31;
    int node = (blockIdx.x * blockDim.x + threadIdx.x) >> 5;
    if (node >= n) return;
    double mu = ss[lane] / (double)n;
    float sd = rsqrtf((float)(sq[lane] / (double)n - mu * mu) + BN_EPS);
    float z = ((float*)g_Z)[node * HD + lane];
    float h = fmaxf(g[lane] * ((z - (float)mu) * sd) + be[lane], 0.0f);
    float v = h * fcW[lane];
    #pragma unroll
    for (int o = 16; o > 0; o >>= 1) v += __shfl_xor_sync(0xffffffffu, v, o);
    if (lane == 0) out[node] = v + fcb[0];
}

extern "C" void kernel_launch(void* const* d_in, const int* in_sizes, int n_in,
                              void* d_out, int out_size) {
    const float* x   = (const float*)d_in[0];
    const int*   ei  = (const int*)d_in[1];     // int32 edge_index
    const float* W1  = (const float*)d_in[3];
    const float* g1  = (const float*)d_in[5];
    const float* be1 = (const float*)d_in[6];
    const float* W2  = (const float*)d_in[7];
    const float* b2  = (const float*)d_in[8];
    const float* g2  = (const float*)d_in[9];
    const float* be2 = (const float*)d_in[10];
    const float* W3  = (const float*)d_in[11];
    const float* b3  = (const float*)d_in[12];
    const float* g3  = (const float*)d_in[13];
    const float* be3 = (const float*)d_in[14];
    const float* fcW = (const float*)d_in[15];
    const float* fcb = (const float*)d_in[16];
    float* out = (float*)d_out;

    int n = in_sizes[0];
    int E = in_sizes[1] / 2;
    const int* src = ei;
    const int* dst = ei + E;

    void *pdeg, *pstats;
    cudaGetSymbolAddress(&pdeg,   g_deg);
    cudaGetSymbolAddress(&pstats, g_stats);
    double* stats = (double*)pstats;

    const int T = 256;
    int bE  = (E + T - 1) / T;
    int nb  = (n + 1023) / 1024;         // scan chunks (<=256)
    int bNW = (n * HD + T - 1) / T;      // warp-per-node dense kernels
    int bG  = 1184;                       // gather grid (8 blocks/SM)

    cudaMemsetAsync(pdeg,   0, (size_t)n * sizeof(int));
    cudaMemsetAsync(pstats, 0, 130 * sizeof(double));

    // CSR build
    k_deg<<<bE, T>>>(dst, E);
    k_scanA<<<nb, T>>>(n);
    k_scanB<<<1, 256>>>(nb);
    k_scanC<<<nb, T>>>(x, n);
    k_fill<<<bE, T>>>(src, dst, E);

    // layer 1 (scalar gather)
    k_gscal<<<bG, T>>>(x, n);
    k_layer1<<<bNW, T>>>(W1, g1, be1, W2, n);

    // layer 2
    k_gath<<<bG, T>>>(b2, stats + 2, stats + 34, n);
    k_mid<<<bNW, T>>>(g2, be2, W3, stats + 2, stats + 34, n);

    // layer 3
    k_gath<<<bG, T>>>(b3, stats + 66, stats + 98, n);

    // output
    k_out<<<bNW, T>>>(g3, be3, fcW, fcb, stats + 66, stats + 98, n, out);
}

// round 4
// speedup vs baseline: 2.2300x; 2.0976x over previous
#include <cuda_runtime.h>

#define N_NODES 200000
#define E_MAX   2500000
#define HD      32
#define BN_EPS  1e-5f
#define NB      592          // grid blocks (148 SM x 4, all co-resident)
#define NT      256          // threads per block
#define NWARPS  (NB * 8)

// ---- persistent scratch (__device__ globals; allocations forbidden) ----
__device__ unsigned g_tick;           // monotonic barrier ticket (replay-safe)
__device__ int    g_deg[N_NODES];
__device__ int    g_off[N_NODES];
__device__ int    g_cur[N_NODES];
__device__ int    g_adj[E_MAX];
__device__ int    g_bsum[NB];
__device__ int    g_boff[NB];
__device__ float  g_norm[N_NODES];
__device__ float  g_xn[N_NODES];
__device__ float  g_s[N_NODES];
__device__ float  g_U2[N_NODES * HD];
__device__ float  g_U3[N_NODES * HD];
__device__ float  g_Z2[N_NODES * HD];
__device__ float  g_Z3[N_NODES * HD];
__device__ double g_stats[130];       // [0,1]=L1 ; [2..65]=L2 ; [66..129]=L3

// ---- device-wide barrier: monotonic ticket, no reset, replay-safe ----
__device__ __forceinline__ void gbar() {
    __syncthreads();
    if (threadIdx.x == 0) {
        __threadfence();
        unsigned nb = gridDim.x;
        unsigned t = atomicAdd(&g_tick, 1u) + 1u;
        unsigned need = ((t + nb - 1u) / nb) * nb;
        while (*((volatile unsigned*)&g_tick) < need) { __nanosleep(64); }
    }
    __syncthreads();
}

__global__ void k_pad() {}   // ncu alignment pads

// ---- 32-wide gather: Z = norm*(sum U[adj] + U[self]) + b ; column stats ----
__device__ __forceinline__ void gather32(const float* __restrict__ U, float* __restrict__ Z,
                                         const float* __restrict__ bvec,
                                         double* ss, double* sq, int n,
                                         double* shd, double* shd2) {
    int lane = threadIdx.x & 31;
    int gw = blockIdx.x * 8 + (threadIdx.x >> 5);
    float bj = bvec[lane];
    double a = 0.0, a2 = 0.0;
    for (int node = gw; node < n; node += NWARPS) {
        int beg = g_off[node], deg = g_deg[node];
        int m = deg < 32 ? deg : 32;
        int idx = (lane < deg) ? g_adj[beg + lane] : 0;
        float acc = 0.0f;
        int j = 0;
        for (; j + 4 <= m; j += 4) {
            int s0 = __shfl_sync(0xffffffffu, idx, j);
            int s1 = __shfl_sync(0xffffffffu, idx, j + 1);
            int s2 = __shfl_sync(0xffffffffu, idx, j + 2);
            int s3 = __shfl_sync(0xffffffffu, idx, j + 3);
            acc += U[s0 * HD + lane] + U[s1 * HD + lane]
                 + U[s2 * HD + lane] + U[s3 * HD + lane];
        }
        for (; j < m; j++) {
            int s = __shfl_sync(0xffffffffu, idx, j);
            acc += U[s * HD + lane];
        }
        for (j = 32; j < deg; j++) acc += U[g_adj[beg + j] * HD + lane];  // rare tail
        float z = g_norm[node] * (acc + U[node * HD + lane]) + bj;
        Z[node * HD + lane] = z;
        a += (double)z; a2 += (double)z * (double)z;
    }
    shd[threadIdx.x] = a; shd2[threadIdx.x] = a2;
    __syncthreads();
    if (threadIdx.x < 32) {
        double s = 0.0, s2 = 0.0;
        #pragma unroll
        for (int k = 0; k < 8; k++) { s += shd[k * 32 + threadIdx.x]; s2 += shd2[k * 32 + threadIdx.x]; }
        atomicAdd(&ss[threadIdx.x], s);
        atomicAdd(&sq[threadIdx.x], s2);
    }
    __syncthreads();
}

// ---- dense: h = relu(bn(Zin)), Uout = (h @ Wn) * norm ----
__device__ __forceinline__ void dense(const float* __restrict__ Zin, float* __restrict__ Uout,
                                      const float* __restrict__ g, const float* __restrict__ be,
                                      const float* __restrict__ Wn,
                                      const double* ss, const double* sq, int n, float* sW) {
    for (int i = threadIdx.x; i < HD * HD; i += NT) sW[i] = Wn[i];
    __syncthreads();
    int lane = threadIdx.x & 31;
    int gw = blockIdx.x * 8 + (threadIdx.x >> 5);
    double mu = ss[lane] / (double)n;
    float sd = rsqrtf((float)(sq[lane] / (double)n - mu * mu) + BN_EPS);
    float mean = (float)mu, gl = g[lane], bl = be[lane];
    for (int node = gw; node < n; node += NWARPS) {
        float z = Zin[node * HD + lane];
        float h = fmaxf(gl * ((z - mean) * sd) + bl, 0.0f);
        float t = 0.0f;
        #pragma unroll
        for (int k = 0; k < HD; k++)
            t += __shfl_sync(0xffffffffu, h, k) * sW[k * HD + lane];
        Uout[node * HD + lane] = t * g_norm[node];
    }
    __syncthreads();
}

__global__ void __launch_bounds__(NT, 4)
k_mega(const float* __restrict__ x, const int* __restrict__ src, const int* __restrict__ dst,
       const float* __restrict__ W1, const float* __restrict__ g1, const float* __restrict__ be1,
       const float* __restrict__ W2, const float* __restrict__ b2, const float* __restrict__ g2,
       const float* __restrict__ be2, const float* __restrict__ W3, const float* __restrict__ b3,
       const float* __restrict__ g3, const float* __restrict__ be3,
       const float* __restrict__ fcW, const float* __restrict__ fcb,
       float* __restrict__ out, int n, int E) {
    __shared__ float  sW[HD * HD];
    __shared__ double shd[NT], shd2[NT];
    __shared__ int    shi[NT];

    int tid = threadIdx.x;
    int gt  = blockIdx.x * NT + tid;
    int lane = tid & 31, wid = tid >> 5;
    int gw = blockIdx.x * 8 + wid;

    // ---- P0: zero scratch ----
    for (int i = gt; i < n; i += NB * NT) g_deg[i] = 0;
    if (gt < 130) g_stats[gt] = 0.0;
    gbar();

    // ---- P1: degree histogram ----
    for (int e = gt; e < E; e += NB * NT) atomicAdd(&g_deg[dst[e]], 1);
    gbar();

    // ---- P2a: per-block-range degree sums ----
    int C = (n + NB - 1) / NB;                      // 338 for n=200000 (<=512)
    int base = blockIdx.x * C;
    int hi = min(n, base + C);
    {
        int s = 0;
        for (int i = base + tid; i < hi; i += NT) s += g_deg[i];
        for (int o = 16; o > 0; o >>= 1) s += __shfl_xor_sync(0xffffffffu, s, o);
        if (lane == 0) shi[wid] = s;
        __syncthreads();
        if (tid == 0) {
            int t = 0;
            #pragma unroll
            for (int k = 0; k < 8; k++) t += shi[k];
            g_bsum[blockIdx.x] = t;
        }
    }
    gbar();

    // ---- P2b: block 0 exclusive-scans NB chunk sums ----
    if (blockIdx.x == 0) {
        int v0 = (3 * tid     < NB) ? g_bsum[3 * tid]     : 0;
        int v1 = (3 * tid + 1 < NB) ? g_bsum[3 * tid + 1] : 0;
        int v2 = (3 * tid + 2 < NB) ? g_bsum[3 * tid + 2] : 0;
        int s = v0 + v1 + v2;
        shi[tid] = s;
        __syncthreads();
        for (int o = 1; o < NT; o <<= 1) {
            int t = (tid >= o) ? shi[tid - o] : 0;
            __syncthreads();
            shi[tid] += t;
            __syncthreads();
        }
        int excl = shi[tid] - s;
        if (3 * tid     < NB) g_boff[3 * tid]     = excl;
        if (3 * tid + 1 < NB) g_boff[3 * tid + 1] = excl + v0;
        if (3 * tid + 2 < NB) g_boff[3 * tid + 2] = excl + v0 + v1;
    }
    gbar();

    // ---- P2c: per-node offsets + norm + xn (block-local scan, 2 nodes/thread) ----
    {
        int i0 = base + tid * 2, i1 = i0 + 1;
        int d0 = (i0 < hi) ? g_deg[i0] : 0;
        int d1 = (i1 < hi) ? g_deg[i1] : 0;
        int s = d0 + d1;
        shi[tid] = s;
        __syncthreads();
        for (int o = 1; o < NT; o <<= 1) {
            int t = (tid >= o) ? shi[tid - o] : 0;
            __syncthreads();
            shi[tid] += t;
            __syncthreads();
        }
        int run = g_boff[blockIdx.x] + shi[tid] - s;
        if (i0 < hi) {
            g_off[i0] = run; g_cur[i0] = run;
            float nr = rsqrtf((float)d0 + 1.0f);
            g_norm[i0] = nr; g_xn[i0] = x[i0] * nr;
        }
        if (i1 < hi) {
            int r1 = run + d0;
            g_off[i1] = r1; g_cur[i1] = r1;
            float nr = rsqrtf((float)d1 + 1.0f);
            g_norm[i1] = nr; g_xn[i1] = x[i1] * nr;
        }
    }
    gbar();

    // ---- P3: CSR fill ----
    for (int e = gt; e < E; e += NB * NT) {
        int pos = atomicAdd(&g_cur[dst[e]], 1);
        g_adj[pos] = src[e];
    }
    gbar();

    // ---- P4: layer-1 scalar gather + stats ----
    {
        double a = 0.0, a2 = 0.0;
        for (int node = gw; node < n; node += NWARPS) {
            int beg = g_off[node], deg = g_deg[node];
            float acc = 0.0f;
            for (int j = lane; j < deg; j += 32) acc += g_xn[g_adj[beg + j]];
            for (int o = 16; o > 0; o >>= 1) acc += __shfl_xor_sync(0xffffffffu, acc, o);
            if (lane == 0) {
                float nr = g_norm[node];
                float s = nr * acc + x[node] * nr * nr;
                g_s[node] = s;
                a += (double)s; a2 += (double)s * (double)s;
            }
        }
        shd[tid] = a; shd2[tid] = a2;
        __syncthreads();
        for (int o = 128; o > 0; o >>= 1) {
            if (tid < o) { shd[tid] += shd[tid + o]; shd2[tid] += shd2[tid + o]; }
            __syncthreads();
        }
        if (tid == 0) { atomicAdd(&g_stats[0], shd[0]); atomicAdd(&g_stats[1], shd2[0]); }
    }
    gbar();

    // ---- P5: layer-1 dense -> U2 ----
    {
        for (int i = tid; i < HD * HD; i += NT) sW[i] = W2[i];
        __syncthreads();
        double mu = g_stats[0] / (double)n;
        double vr = g_stats[1] / (double)n - mu * mu;
        float w = W1[lane];
        float aa = g1[lane] * w * rsqrtf((float)vr * w * w + BN_EPS);
        float mean = (float)mu, bl = be1[lane];
        for (int node = gw; node < n; node += NWARPS) {
            float h = fmaxf(aa * (g_s[node] - mean) + bl, 0.0f);
            float t = 0.0f;
            #pragma unroll
            for (int k = 0; k < HD; k++)
                t += __shfl_sync(0xffffffffu, h, k) * sW[k * HD + lane];
            g_U2[node * HD + lane] = t * g_norm[node];
        }
        __syncthreads();
    }
    gbar();

    // ---- P6: layer-2 gather -> Z2 ----
    gather32(g_U2, g_Z2, b2, &g_stats[2], &g_stats[34], n, shd, shd2);
    gbar();

    // ---- P7: layer-2 dense -> U3 ----
    dense(g_Z2, g_U3, g2, be2, W3, &g_stats[2], &g_stats[34], n, sW);
    gbar();

    // ---- P8: layer-3 gather -> Z3 ----
    gather32(g_U3, g_Z3, b3, &g_stats[66], &g_stats[98], n, shd, shd2);
    gbar();

    // ---- P9: output ----
    {
        double mu = g_stats[66 + lane] / (double)n;
        float sd = rsqrtf((float)(g_stats[98 + lane] / (double)n - mu * mu) + BN_EPS);
        float mean = (float)mu, gl = g3[lane], bl = be3[lane], fw = fcW[lane], fb = fcb[0];
        for (int node = gw; node < n; node += NWARPS) {
            float z = g_Z3[node * HD + lane];
            float h = fmaxf(gl * ((z - mean) * sd) + bl, 0.0f);
            float v = h * fw;
            #pragma unroll
            for (int o = 16; o > 0; o >>= 1) v += __shfl_xor_sync(0xffffffffu, v, o);
            if (lane == 0) out[node] = v + fb;
        }
    }
}

extern "C" void kernel_launch(void* const* d_in, const int* in_sizes, int n_in,
                              void* d_out, int out_size) {
    const float* x   = (const float*)d_in[0];
    const int*   ei  = (const int*)d_in[1];     // int32 edge_index
    const float* W1  = (const float*)d_in[3];
    const float* g1  = (const float*)d_in[5];
    const float* be1 = (const float*)d_in[6];
    const float* W2  = (const float*)d_in[7];
    const float* b2  = (const float*)d_in[8];
    const float* g2  = (const float*)d_in[9];
    const float* be2 = (const float*)d_in[10];
    const float* W3  = (const float*)d_in[11];
    const float* b3  = (const float*)d_in[12];
    const float* g3  = (const float*)d_in[13];
    const float* be3 = (const float*)d_in[14];
    const float* fcW = (const float*)d_in[15];
    const float* fcb = (const float*)d_in[16];
    float* out = (float*)d_out;

    int n = in_sizes[0];
    int E = in_sizes[1] / 2;
    const int* src = ei;
    const int* dst = ei + E;

    // 5 pads so ncu (-s 5 -c 1) captures the mega kernel
    k_pad<<<1, 32>>>(); k_pad<<<1, 32>>>(); k_pad<<<1, 32>>>();
    k_pad<<<1, 32>>>(); k_pad<<<1, 32>>>();

    k_mega<<<NB, NT>>>(x, src, dst, W1, g1, be1, W2, b2, g2, be2,
                       W3, b3, g3, be3, fcW, fcb, out, n, E);
}

// round 6
// speedup vs baseline: 2.3256x; 1.0429x over previous
#include <cuda_runtime.h>

#define N_NODES 200000
#define E_MAX   2500000
#define HD      32
#define BN_EPS  1e-5f
#define NB      592          // 148 SM x 4, all co-resident
#define NT      256
#define NWARPS  (NB * 8)
#define NGRP    (NB * 32)    // 8-lane groups

// ---- persistent scratch ----
__device__ unsigned g_tick;
__device__ int    g_deg[N_NODES];
__device__ int    g_off[N_NODES];
__device__ int    g_cur[N_NODES];
__device__ int    g_adj[E_MAX];
__device__ int    g_bsum[NB];
__device__ int    g_boff[NB];
__device__ float  g_norm[N_NODES];
__device__ float  g_xn[N_NODES];
__device__ float  g_s[N_NODES];
__device__ float4 g_U2[N_NODES * 8];
__device__ float4 g_U3[N_NODES * 8];
__device__ float4 g_Z2[N_NODES * 8];
__device__ float4 g_Z3[N_NODES * 8];
__device__ double g_stats[130];       // [0,1]=L1 ; [2..65]=L2 ; [66..129]=L3

// ---- device-wide barrier (monotonic ticket; graph-replay-safe) ----
__device__ __forceinline__ void gbar() {
    __threadfence();
    __syncthreads();
    if (threadIdx.x == 0) {
        unsigned nb = gridDim.x;
        unsigned t = atomicAdd(&g_tick, 1u) + 1u;
        unsigned need = ((t + nb - 1u) / nb) * nb;
        while (*((volatile unsigned*)&g_tick) < need) { __nanosleep(64); }
    }
    __syncthreads();
}

// ---- gather v2: 8-lane groups, float4, 4 nodes/warp ----
// Z4[node] = norm*(sum_{s in adj} U4[s] + U4[node]) + b ; per-feature stats
__device__ __forceinline__ void gather32(const float4* __restrict__ U, float4* __restrict__ Z,
                                         const float* __restrict__ bvec,
                                         double* ss, double* sq, int n, double* shd) {
    int tid = threadIdx.x;
    int lane = tid & 31;
    int q = tid & 7;                           // sublane within group
    unsigned gmask = 0xFFu << (lane & ~7);     // this group's 8 lanes ONLY
    int ggrp = blockIdx.x * 32 + (tid >> 3);   // global group id
    int wid = tid >> 5;
    float4 b4 = ((const float4*)bvec)[q];
    double4 a  = {0.0, 0.0, 0.0, 0.0};
    double4 a2 = {0.0, 0.0, 0.0, 0.0};

    for (int node = ggrp; node < n; node += NGRP) {
        int beg = g_off[node], deg = g_deg[node];
        float4 acc = {0.f, 0.f, 0.f, 0.f};
        for (int j0 = 0; j0 < deg; j0 += 8) {
            int rem = deg - j0;
            int m = rem < 8 ? rem : 8;
            int idx = (q < rem) ? g_adj[beg + j0 + q] : 0;
            #pragma unroll 8
            for (int j = 0; j < 8; j++) {
                if (j >= m) break;
                int s = __shfl_sync(gmask, idx, j, 8);
                float4 v = U[s * 8 + q];
                acc.x += v.x; acc.y += v.y; acc.z += v.z; acc.w += v.w;
            }
        }
        float nr = g_norm[node];
        float4 us = U[node * 8 + q];
        float4 z;
        z.x = nr * (acc.x + us.x) + b4.x;
        z.y = nr * (acc.y + us.y) + b4.y;
        z.z = nr * (acc.z + us.z) + b4.z;
        z.w = nr * (acc.w + us.w) + b4.w;
        Z[node * 8 + q] = z;
        a.x += z.x; a.y += z.y; a.z += z.z; a.w += z.w;
        a2.x += (double)z.x * z.x; a2.y += (double)z.y * z.y;
        a2.z += (double)z.z * z.z; a2.w += (double)z.w * z.w;
    }
    // combine the 4 groups of each warp (lanes with same q): xor 8, 16
    // (all lanes reconverged; executed exactly once -> full-mask legal)
    #pragma unroll
    for (int o = 8; o <= 16; o <<= 1) {
        a.x += __shfl_xor_sync(0xffffffffu, a.x, o);  a.y += __shfl_xor_sync(0xffffffffu, a.y, o);
        a.z += __shfl_xor_sync(0xffffffffu, a.z, o);  a.w += __shfl_xor_sync(0xffffffffu, a.w, o);
        a2.x += __shfl_xor_sync(0xffffffffu, a2.x, o); a2.y += __shfl_xor_sync(0xffffffffu, a2.y, o);
        a2.z += __shfl_xor_sync(0xffffffffu, a2.z, o); a2.w += __shfl_xor_sync(0xffffffffu, a2.w, o);
    }
    __syncthreads();   // reuse shd safely
    if (lane < 8) {
        int base = (wid * 8 + q) * 4;
        shd[base + 0] = a.x; shd[base + 1] = a.y; shd[base + 2] = a.z; shd[base + 3] = a.w;
    }
    __syncthreads();
    if (tid < 32) {
        double s = 0.0;
        #pragma unroll
        for (int w = 0; w < 8; w++) s += shd[(w * 8 + (tid >> 2)) * 4 + (tid & 3)];
        atomicAdd(&ss[tid], s);
    }
    __syncthreads();
    if (lane < 8) {
        int base = (wid * 8 + q) * 4;
        shd[base + 0] = a2.x; shd[base + 1] = a2.y; shd[base + 2] = a2.z; shd[base + 3] = a2.w;
    }
    __syncthreads();
    if (tid < 32) {
        double s = 0.0;
        #pragma unroll
        for (int w = 0; w < 8; w++) s += shd[(w * 8 + (tid >> 2)) * 4 + (tid & 3)];
        atomicAdd(&sq[tid], s);
    }
    __syncthreads();
}

// ---- dense: h = relu(bn(Zin)), Uout = (h @ Wn) * norm  (warp per node) ----
__device__ __forceinline__ void dense(const float* __restrict__ Zin, float* __restrict__ Uout,
                                      const float* __restrict__ g, const float* __restrict__ be,
                                      const float* __restrict__ Wn,
                                      const double* ss, const double* sq, int n, float* sW) {
    for (int i = threadIdx.x; i < HD * HD; i += NT) sW[i] = Wn[i];
    __syncthreads();
    int lane = threadIdx.x & 31;
    int gw = blockIdx.x * 8 + (threadIdx.x >> 5);
    double mu = ss[lane] / (double)n;
    float sd = rsqrtf((float)(sq[lane] / (double)n - mu * mu) + BN_EPS);
    float mean = (float)mu, gl = g[lane], bl = be[lane];
    for (int node = gw; node < n; node += NWARPS) {
        float z = Zin[node * HD + lane];
        float h = fmaxf(gl * ((z - mean) * sd) + bl, 0.0f);
        float t = 0.0f;
        #pragma unroll
        for (int k = 0; k < HD; k++)
            t += __shfl_sync(0xffffffffu, h, k) * sW[k * HD + lane];
        Uout[node * HD + lane] = t * g_norm[node];
    }
    __syncthreads();
}

__global__ void __launch_bounds__(NT, 4)
k_mega(const float* __restrict__ x, const int* __restrict__ src, const int* __restrict__ dst,
       const float* __restrict__ W1, const float* __restrict__ g1, const float* __restrict__ be1,
       const float* __restrict__ W2, const float* __restrict__ b2, const float* __restrict__ g2,
       const float* __restrict__ be2, const float* __restrict__ W3, const float* __restrict__ b3,
       const float* __restrict__ g3, const float* __restrict__ be3,
       const float* __restrict__ fcW, const float* __restrict__ fcb,
       float* __restrict__ out, int n, int E) {
    __shared__ float  sW[HD * HD];
    __shared__ double shd[NT], shd2[NT];
    __shared__ int    shi[NT];

    int tid = threadIdx.x;
    int gt  = blockIdx.x * NT + tid;
    int lane = tid & 31, wid = tid >> 5;
    int gw = blockIdx.x * 8 + wid;

    // ---- P0: zero ----
    for (int i = gt; i < n; i += NB * NT) g_deg[i] = 0;
    if (gt < 130) g_stats[gt] = 0.0;
    gbar();

    // ---- P1: degree histogram ----
    for (int e = gt; e < E; e += NB * NT) atomicAdd(&g_deg[dst[e]], 1);
    gbar();

    // ---- P2a: per-block-range degree sums ----
    int C = (n + NB - 1) / NB;
    int base = blockIdx.x * C;
    int hi = min(n, base + C);
    {
        int s = 0;
        for (int i = base + tid; i < hi; i += NT) s += g_deg[i];
        for (int o = 16; o > 0; o >>= 1) s += __shfl_xor_sync(0xffffffffu, s, o);
        if (lane == 0) shi[wid] = s;
        __syncthreads();
        if (tid == 0) {
            int t = 0;
            #pragma unroll
            for (int k = 0; k < 8; k++) t += shi[k];
            g_bsum[blockIdx.x] = t;
        }
    }
    gbar();

    // ---- P2b: block 0 scans chunk sums ----
    if (blockIdx.x == 0) {
        int v0 = (3 * tid     < NB) ? g_bsum[3 * tid]     : 0;
        int v1 = (3 * tid + 1 < NB) ? g_bsum[3 * tid + 1] : 0;
        int v2 = (3 * tid + 2 < NB) ? g_bsum[3 * tid + 2] : 0;
        int s = v0 + v1 + v2;
        shi[tid] = s;
        __syncthreads();
        for (int o = 1; o < NT; o <<= 1) {
            int t = (tid >= o) ? shi[tid - o] : 0;
            __syncthreads();
            shi[tid] += t;
            __syncthreads();
        }
        int excl = shi[tid] - s;
        if (3 * tid     < NB) g_boff[3 * tid]     = excl;
        if (3 * tid + 1 < NB) g_boff[3 * tid + 1] = excl + v0;
        if (3 * tid + 2 < NB) g_boff[3 * tid + 2] = excl + v0 + v1;
    }
    gbar();

    // ---- P2c: per-node offsets + norm + xn ----
    {
        int i0 = base + tid * 2, i1 = i0 + 1;
        int d0 = (i0 < hi) ? g_deg[i0] : 0;
        int d1 = (i1 < hi) ? g_deg[i1] : 0;
        int s = d0 + d1;
        shi[tid] = s;
        __syncthreads();
        for (int o = 1; o < NT; o <<= 1) {
            int t = (tid >= o) ? shi[tid - o] : 0;
            __syncthreads();
            shi[tid] += t;
            __syncthreads();
        }
        int run = g_boff[blockIdx.x] + shi[tid] - s;
        if (i0 < hi) {
            g_off[i0] = run; g_cur[i0] = run;
            float nr = rsqrtf((float)d0 + 1.0f);
            g_norm[i0] = nr; g_xn[i0] = x[i0] * nr;
        }
        if (i1 < hi) {
            int r1 = run + d0;
            g_off[i1] = r1; g_cur[i1] = r1;
            float nr = rsqrtf((float)d1 + 1.0f);
            g_norm[i1] = nr; g_xn[i1] = x[i1] * nr;
        }
    }
    gbar();

    // ---- P3: CSR fill ----
    for (int e = gt; e < E; e += NB * NT) {
        int pos = atomicAdd(&g_cur[dst[e]], 1);
        g_adj[pos] = src[e];
    }
    gbar();

    // ---- P4: layer-1 scalar gather + stats ----
    {
        double a = 0.0, a2 = 0.0;
        for (int node = gw; node < n; node += NWARPS) {
            int beg = g_off[node], deg = g_deg[node];
            float acc = 0.0f;
            for (int j = lane; j < deg; j += 32) acc += g_xn[g_adj[beg + j]];
            for (int o = 16; o > 0; o >>= 1) acc += __shfl_xor_sync(0xffffffffu, acc, o);
            if (lane == 0) {
                float nr = g_norm[node];
                float s = nr * acc + x[node] * nr * nr;
                g_s[node] = s;
                a += (double)s; a2 += (double)s * (double)s;
            }
        }
        shd[tid] = a; shd2[tid] = a2;
        __syncthreads();
        for (int o = 128; o > 0; o >>= 1) {
            if (tid < o) { shd[tid] += shd[tid + o]; shd2[tid] += shd2[tid + o]; }
            __syncthreads();
        }
        if (tid == 0) { atomicAdd(&g_stats[0], shd[0]); atomicAdd(&g_stats[1], shd2[0]); }
    }
    gbar();

    // ---- P5: layer-1 dense -> U2 ----
    {
        for (int i = tid; i < HD * HD; i += NT) sW[i] = W2[i];
        __syncthreads();
        double mu = g_stats[0] / (double)n;
        double vr = g_stats[1] / (double)n - mu * mu;
        float w = W1[lane];
        float aa = g1[lane] * w * rsqrtf((float)vr * w * w + BN_EPS);
        float mean = (float)mu, bl = be1[lane];
        for (int node = gw; node < n; node += NWARPS) {
            float h = fmaxf(aa * (g_s[node] - mean) + bl, 0.0f);
            float t = 0.0f;
            #pragma unroll
            for (int k = 0; k < HD; k++)
                t += __shfl_sync(0xffffffffu, h, k) * sW[k * HD + lane];
            ((float*)g_U2)[node * HD + lane] = t * g_norm[node];
        }
        __syncthreads();
    }
    gbar();

    // ---- P6: layer-2 gather -> Z2 ----
    gather32(g_U2, g_Z2, b2, &g_stats[2], &g_stats[34], n, shd);
    gbar();

    // ---- P7: layer-2 dense -> U3 ----
    dense((const float*)g_Z2, (float*)g_U3, g2, be2, W3, &g_stats[2], &g_stats[34], n, sW);
    gbar();

    // ---- P8: layer-3 gather -> Z3 ----
    gather32(g_U3, g_Z3, b3, &g_stats[66], &g_stats[98], n, shd);
    gbar();

    // ---- P9: output ----
    {
        double mu = g_stats[66 + lane] / (double)n;
        float sd = rsqrtf((float)(g_stats[98 + lane] / (double)n - mu * mu) + BN_EPS);
        float mean = (float)mu, gl = g3[lane], bl = be3[lane], fw = fcW[lane], fb = fcb[0];
        for (int node = gw; node < n; node += NWARPS) {
            float z = ((const float*)g_Z3)[node * HD + lane];
            float h = fmaxf(gl * ((z - mean) * sd) + bl, 0.0f);
            float v = h * fw;
            #pragma unroll
            for (int o = 16; o > 0; o >>= 1) v += __shfl_xor_sync(0xffffffffu, v, o);
            if (lane == 0) out[node] = v + fb;
        }
    }
}

extern "C" void kernel_launch(void* const* d_in, const int* in_sizes, int n_in,
                              void* d_out, int out_size) {
    const float* x   = (const float*)d_in[0];
    const int*   ei  = (const int*)d_in[1];     // int32 edge_index
    const float* W1  = (const float*)d_in[3];
    const float* g1  = (const float*)d_in[5];
    const float* be1 = (const float*)d_in[6];
    const float* W2  = (const float*)d_in[7];
    const float* b2  = (const float*)d_in[8];
    const float* g2  = (const float*)d_in[9];
    const float* be2 = (const float*)d_in[10];
    const float* W3  = (const float*)d_in[11];
    const float* b3  = (const float*)d_in[12];
    const float* g3  = (const float*)d_in[13];
    const float* be3 = (const float*)d_in[14];
    const float* fcW = (const float*)d_in[15];
    const float* fcb = (const float*)d_in[16];
    float* out = (float*)d_out;

    int n = in_sizes[0];
    int E = in_sizes[1] / 2;
    const int* src = ei;
    const int* dst = ei + E;

    k_mega<<<NB, NT>>>(x, src, dst, W1, g1, be1, W2, b2, g2, be2,
                       W3, b3, g3, be3, fcW, fcb, out, n, E);
}

// round 7
// speedup vs baseline: 3.8120x; 1.6392x over previous
#include <cuda_runtime.h>

#define N_NODES 200000
#define E_PAD   4000000      // E + 7*N worst-case padded CSR
#define HD      32
#define BN_EPS  1e-5f
#define NB      740          // 148 SM x 5, all co-resident
#define NT      256
#define NGRP    (NB * 32)    // 8-lane groups

// ---- persistent scratch ----
__device__ unsigned g_tick;
__device__ int    g_deg[N_NODES];
__device__ int    g_off[N_NODES];
__device__ int    g_cur[N_NODES];
__device__ int    g_adj[E_PAD];
__device__ int    g_bsum[NB];
__device__ int    g_boff[NB];
__device__ float  g_norm[N_NODES];
__device__ float  g_xn[N_NODES + 1];        // +1: dummy row = 0
__device__ float  g_s[N_NODES];
__device__ float4 g_U2[(N_NODES + 1) * 8];  // +1: dummy row = 0
__device__ float4 g_U3[(N_NODES + 1) * 8];
__device__ float4 g_Z2[N_NODES * 8];
__device__ float4 g_Z3[N_NODES * 8];
__device__ double g_stats[130];             // [0,1]=L1 ; [2..65]=L2 ; [66..129]=L3

// ---- device-wide barrier (monotonic ticket; graph-replay-safe) ----
__device__ __forceinline__ void gbar() {
    __threadfence();
    __syncthreads();
    if (threadIdx.x == 0) {
        unsigned nb = gridDim.x;
        unsigned t = atomicAdd(&g_tick, 1u) + 1u;
        unsigned need = ((t + nb - 1u) / nb) * nb;
        while (*((volatile unsigned*)&g_tick) < need) { __nanosleep(64); }
    }
    __syncthreads();
}

// ---- gather: 8-lane group per node, padded branch-free inner, float stats ----
__device__ __forceinline__ void gatherG(const float4* __restrict__ U, float4* __restrict__ Z,
                                        const float* __restrict__ bvec,
                                        double* ss, double* sq, int n, double* shd) {
    int tid = threadIdx.x, lane = tid & 31, q = tid & 7, wid = tid >> 5;
    int ggrp = blockIdx.x * 32 + (tid >> 3);
    float4 b4 = ((const float4*)bvec)[q];
    float4 a  = {0.f, 0.f, 0.f, 0.f};
    float4 a2 = {0.f, 0.f, 0.f, 0.f};

    for (int node = ggrp; node < n; node += NGRP) {
        int beg = g_off[node];
        int pd  = (g_deg[node] + 7) & ~7;
        const int4* ap = (const int4*)(g_adj + beg);   // 32B-aligned (beg mult of 8)
        float4 acc = {0.f, 0.f, 0.f, 0.f};
        for (int t = 0; t < pd; t += 8) {
            int4 i0 = ap[0], i1 = ap[1]; ap += 2;      // broadcast loads (uniform addr)
            float4 v0 = U[i0.x * 8 + q], v1 = U[i0.y * 8 + q];
            float4 v2 = U[i0.z * 8 + q], v3 = U[i0.w * 8 + q];
            float4 v4 = U[i1.x * 8 + q], v5 = U[i1.y * 8 + q];
            float4 v6 = U[i1.z * 8 + q], v7 = U[i1.w * 8 + q];
            acc.x += ((v0.x + v1.x) + (v2.x + v3.x)) + ((v4.x + v5.x) + (v6.x + v7.x));
            acc.y += ((v0.y + v1.y) + (v2.y + v3.y)) + ((v4.y + v5.y) + (v6.y + v7.y));
            acc.z += ((v0.z + v1.z) + (v2.z + v3.z)) + ((v4.z + v5.z) + (v6.z + v7.z));
            acc.w += ((v0.w + v1.w) + (v2.w + v3.w)) + ((v4.w + v5.w) + (v6.w + v7.w));
        }
        float nr = g_norm[node];
        float4 us = U[node * 8 + q];
        float4 z;
        z.x = nr * (acc.x + us.x) + b4.x;
        z.y = nr * (acc.y + us.y) + b4.y;
        z.z = nr * (acc.z + us.z) + b4.z;
        z.w = nr * (acc.w + us.w) + b4.w;
        Z[node * 8 + q] = z;
        a.x += z.x; a.y += z.y; a.z += z.z; a.w += z.w;
        a2.x += z.x * z.x; a2.y += z.y * z.y; a2.z += z.z * z.z; a2.w += z.w * z.w;
    }
    // combine 4 groups of the warp (full-mask legal: each lane executes once)
    #pragma unroll
    for (int o = 8; o <= 16; o <<= 1) {
        a.x += __shfl_xor_sync(0xffffffffu, a.x, o);   a.y += __shfl_xor_sync(0xffffffffu, a.y, o);
        a.z += __shfl_xor_sync(0xffffffffu, a.z, o);   a.w += __shfl_xor_sync(0xffffffffu, a.w, o);
        a2.x += __shfl_xor_sync(0xffffffffu, a2.x, o); a2.y += __shfl_xor_sync(0xffffffffu, a2.y, o);
        a2.z += __shfl_xor_sync(0xffffffffu, a2.z, o); a2.w += __shfl_xor_sync(0xffffffffu, a2.w, o);
    }
    __syncthreads();
    if (lane < 8) {
        int b = (wid * 8 + q) * 4;
        shd[b] = a.x; shd[b + 1] = a.y; shd[b + 2] = a.z; shd[b + 3] = a.w;
    }
    __syncthreads();
    if (tid < 32) {
        double s = 0.0;
        #pragma unroll
        for (int w = 0; w < 8; w++) s += shd[(w * 8 + (tid >> 2)) * 4 + (tid & 3)];
        atomicAdd(&ss[tid], s);
    }
    __syncthreads();
    if (lane < 8) {
        int b = (wid * 8 + q) * 4;
        shd[b] = a2.x; shd[b + 1] = a2.y; shd[b + 2] = a2.z; shd[b + 3] = a2.w;
    }
    __syncthreads();
    if (tid < 32) {
        double s = 0.0;
        #pragma unroll
        for (int w = 0; w < 8; w++) s += shd[(w * 8 + (tid >> 2)) * 4 + (tid & 3)];
        atomicAdd(&sq[tid], s);
    }
    __syncthreads();
}

// ---- dense: h = relu(bn(Zin)), Uout = (h @ Wn)*norm ; 4 nodes/warp ----
__device__ __forceinline__ void denseG(const float4* __restrict__ Zin, float4* __restrict__ Uout,
                                       const float* __restrict__ gv, const float* __restrict__ bev,
                                       const float* __restrict__ Wn,
                                       const double* ss, const double* sq, int n, float4* sW4) {
    for (int i = threadIdx.x; i < 256; i += NT) sW4[i] = ((const float4*)Wn)[i];
    __syncthreads();
    int q = threadIdx.x & 7;
    unsigned gmask = 0xFFu << ((threadIdx.x & 31) & ~7);
    int ggrp = blockIdx.x * 32 + (threadIdx.x >> 3);
    float4 gl = ((const float4*)gv)[q], bl = ((const float4*)bev)[q];
    float4 mean, sd;
    {
        double inv = 1.0 / (double)n;
        double m0 = ss[4*q+0]*inv, m1 = ss[4*q+1]*inv, m2 = ss[4*q+2]*inv, m3 = ss[4*q+3]*inv;
        sd.x = rsqrtf((float)(sq[4*q+0]*inv - m0*m0) + BN_EPS);
        sd.y = rsqrtf((float)(sq[4*q+1]*inv - m1*m1) + BN_EPS);
        sd.z = rsqrtf((float)(sq[4*q+2]*inv - m2*m2) + BN_EPS);
        sd.w = rsqrtf((float)(sq[4*q+3]*inv - m3*m3) + BN_EPS);
        mean.x = (float)m0; mean.y = (float)m1; mean.z = (float)m2; mean.w = (float)m3;
    }
    for (int node = ggrp; node < n; node += NGRP) {
        float4 z = Zin[node * 8 + q];
        float4 h;
        h.x = fmaxf(gl.x * ((z.x - mean.x) * sd.x) + bl.x, 0.f);
        h.y = fmaxf(gl.y * ((z.y - mean.y) * sd.y) + bl.y, 0.f);
        h.z = fmaxf(gl.z * ((z.z - mean.z) * sd.z) + bl.z, 0.f);
        h.w = fmaxf(gl.w * ((z.w - mean.w) * sd.w) + bl.w, 0.f);
        float4 t = {0.f, 0.f, 0.f, 0.f};
        #pragma unroll
        for (int k = 0; k < 32; k++) {
            float hk = ((k & 3) == 0) ? h.x : ((k & 3) == 1) ? h.y : ((k & 3) == 2) ? h.z : h.w;
            hk = __shfl_sync(gmask, hk, k >> 2, 8);
            float4 w = sW4[k * 8 + q];
            t.x += hk * w.x; t.y += hk * w.y; t.z += hk * w.z; t.w += hk * w.w;
        }
        float nr = g_norm[node];
        float4 o; o.x = t.x * nr; o.y = t.y * nr; o.z = t.z * nr; o.w = t.w * nr;
        Uout[node * 8 + q] = o;
    }
    __syncthreads();
}

__global__ void __launch_bounds__(NT, 5)
k_mega(const float* __restrict__ x, const int* __restrict__ src, const int* __restrict__ dst,
       const float* __restrict__ W1, const float* __restrict__ g1, const float* __restrict__ be1,
       const float* __restrict__ W2, const float* __restrict__ b2, const float* __restrict__ g2,
       const float* __restrict__ be2, const float* __restrict__ W3, const float* __restrict__ b3,
       const float* __restrict__ g3, const float* __restrict__ be3,
       const float* __restrict__ fcW, const float* __restrict__ fcb,
       float* __restrict__ out, int n, int E) {
    __shared__ float4 sW4[256];
    __shared__ double shd[NT];
    __shared__ int    shi[NT];

    int tid = threadIdx.x;
    int gt  = blockIdx.x * NT + tid;
    int lane = tid & 31, wid = tid >> 5;
    int q = tid & 7;
    unsigned gmask = 0xFFu << (lane & ~7);
    int ggrp = blockIdx.x * 32 + (tid >> 3);

    // ---- P0: zero deg/stats, zero dummy rows ----
    for (int i = gt; i < n; i += NB * NT) g_deg[i] = 0;
    if (gt < 130) g_stats[gt] = 0.0;
    if (gt >= 130 && gt < 138) {
        float4 zz = {0.f, 0.f, 0.f, 0.f};
        g_U2[n * 8 + (gt - 130)] = zz;
        g_U3[n * 8 + (gt - 130)] = zz;
    }
    if (gt == 138) g_xn[n] = 0.f;
    gbar();

    // ---- P1: degree histogram ----
    for (int e = gt; e < E; e += NB * NT) atomicAdd(&g_deg[dst[e]], 1);
    gbar();

    // ---- P2a: per-block-range PADDED degree sums ----
    int C = (n + NB - 1) / NB;
    int base = blockIdx.x * C;
    int hi = min(n, base + C);
    {
        int s = 0;
        for (int i = base + tid; i < hi; i += NT) s += (g_deg[i] + 7) & ~7;
        for (int o = 16; o > 0; o >>= 1) s += __shfl_xor_sync(0xffffffffu, s, o);
        if (lane == 0) shi[wid] = s;
        __syncthreads();
        if (tid == 0) {
            int t = 0;
            #pragma unroll
            for (int k = 0; k < 8; k++) t += shi[k];
            g_bsum[blockIdx.x] = t;
        }
    }
    gbar();

    // ---- P2b: block 0 scans chunk sums ----
    if (blockIdx.x == 0) {
        int v0 = (3 * tid     < NB) ? g_bsum[3 * tid]     : 0;
        int v1 = (3 * tid + 1 < NB) ? g_bsum[3 * tid + 1] : 0;
        int v2 = (3 * tid + 2 < NB) ? g_bsum[3 * tid + 2] : 0;
        int s = v0 + v1 + v2;
        shi[tid] = s;
        __syncthreads();
        for (int o = 1; o < NT; o <<= 1) {
            int t = (tid >= o) ? shi[tid - o] : 0;
            __syncthreads();
            shi[tid] += t;
            __syncthreads();
        }
        int excl = shi[tid] - s;
        if (3 * tid     < NB) g_boff[3 * tid]     = excl;
        if (3 * tid + 1 < NB) g_boff[3 * tid + 1] = excl + v0;
        if (3 * tid + 2 < NB) g_boff[3 * tid + 2] = excl + v0 + v1;
    }
    gbar();

    // ---- P2c: per-node padded offsets + norm + xn + pad-fill with dummy ----
    {
        int i0 = base + tid * 2, i1 = i0 + 1;
        int d0 = (i0 < hi) ? g_deg[i0] : 0;
        int d1 = (i1 < hi) ? g_deg[i1] : 0;
        int p0 = (d0 + 7) & ~7, p1 = (d1 + 7) & ~7;
        int s = p0 + p1;
        shi[tid] = s;
        __syncthreads();
        for (int o = 1; o < NT; o <<= 1) {
            int t = (tid >= o) ? shi[tid - o] : 0;
            __syncthreads();
            shi[tid] += t;
            __syncthreads();
        }
        int run = g_boff[blockIdx.x] + shi[tid] - s;
        if (i0 < hi) {
            g_off[i0] = run; g_cur[i0] = run;
            float nr = rsqrtf((float)d0 + 1.0f);
            g_norm[i0] = nr; g_xn[i0] = x[i0] * nr;
            for (int w = d0; w < p0; w++) g_adj[run + w] = n;   // dummy pad
        }
        if (i1 < hi) {
            int r1 = run + p0;
            g_off[i1] = r1; g_cur[i1] = r1;
            float nr = rsqrtf((float)d1 + 1.0f);
            g_norm[i1] = nr; g_xn[i1] = x[i1] * nr;
            for (int w = d1; w < p1; w++) g_adj[r1 + w] = n;
        }
    }
    gbar();

    // ---- P3: CSR fill ----
    for (int e = gt; e < E; e += NB * NT) {
        int pos = atomicAdd(&g_cur[dst[e]], 1);
        g_adj[pos] = src[e];
    }
    gbar();

    // ---- P4: layer-1 scalar gather (8-lane groups) + stats ----
    {
        float a = 0.f, a2 = 0.f;
        for (int node = ggrp; node < n; node += NGRP) {
            int beg = g_off[node];
            int pd = (g_deg[node] + 7) & ~7;
            float acc = 0.f;
            for (int j0 = 0; j0 < pd; j0 += 8) acc += g_xn[g_adj[beg + j0 + q]];
            acc += __shfl_xor_sync(gmask, acc, 4, 8);
            acc += __shfl_xor_sync(gmask, acc, 2, 8);
            acc += __shfl_xor_sync(gmask, acc, 1, 8);
            if (q == 0) {
                float nr = g_norm[node];
                float sv = nr * acc + x[node] * nr * nr;
                g_s[node] = sv;
                a += sv; a2 += sv * sv;
            }
        }
        a  += __shfl_xor_sync(0xffffffffu, a, 8);  a  += __shfl_xor_sync(0xffffffffu, a, 16);
        a2 += __shfl_xor_sync(0xffffffffu, a2, 8); a2 += __shfl_xor_sync(0xffffffffu, a2, 16);
        __syncthreads();
        if (lane == 0) { shd[wid] = (double)a; shd[8 + wid] = (double)a2; }
        __syncthreads();
        if (tid == 0) {
            double s1 = 0.0, s2 = 0.0;
            #pragma unroll
            for (int k = 0; k < 8; k++) { s1 += shd[k]; s2 += shd[8 + k]; }
            atomicAdd(&g_stats[0], s1); atomicAdd(&g_stats[1], s2);
        }
        __syncthreads();
    }
    gbar();

    // ---- P5: layer-1 dense -> U2 (4 nodes/warp) ----
    {
        for (int i = tid; i < 256; i += NT) sW4[i] = ((const float4*)W2)[i];
        __syncthreads();
        double inv = 1.0 / (double)n;
        double mu = g_stats[0] * inv;
        double vr = g_stats[1] * inv - mu * mu;
        float vrf = (float)vr, meanf = (float)mu;
        float4 w4 = ((const float4*)W1)[q];
        float4 gg = ((const float4*)g1)[q], bb = ((const float4*)be1)[q];
        float4 al;
        al.x = gg.x * w4.x * rsqrtf(vrf * w4.x * w4.x + BN_EPS);
        al.y = gg.y * w4.y * rsqrtf(vrf * w4.y * w4.y + BN_EPS);
        al.z = gg.z * w4.z * rsqrtf(vrf * w4.z * w4.z + BN_EPS);
        al.w = gg.w * w4.w * rsqrtf(vrf * w4.w * w4.w + BN_EPS);
        for (int node = ggrp; node < n; node += NGRP) {
            float sv = g_s[node];
            float4 h;
            h.x = fmaxf(al.x * (sv - meanf) + bb.x, 0.f);
            h.y = fmaxf(al.y * (sv - meanf) + bb.y, 0.f);
            h.z = fmaxf(al.z * (sv - meanf) + bb.z, 0.f);
            h.w = fmaxf(al.w * (sv - meanf) + bb.w, 0.f);
            float4 t = {0.f, 0.f, 0.f, 0.f};
            #pragma unroll
            for (int k = 0; k < 32; k++) {
                float hk = ((k & 3) == 0) ? h.x : ((k & 3) == 1) ? h.y : ((k & 3) == 2) ? h.z : h.w;
                hk = __shfl_sync(gmask, hk, k >> 2, 8);
                float4 w = sW4[k * 8 + q];
                t.x += hk * w.x; t.y += hk * w.y; t.z += hk * w.z; t.w += hk * w.w;
            }
            float nr = g_norm[node];
            float4 o; o.x = t.x * nr; o.y = t.y * nr; o.z = t.z * nr; o.w = t.w * nr;
            g_U2[node * 8 + q] = o;
        }
        __syncthreads();
    }
    gbar();

    // ---- P6: layer-2 gather -> Z2 ----
    gatherG(g_U2, g_Z2, b2, &g_stats[2], &g_stats[34], n, shd);
    gbar();

    // ---- P7: layer-2 dense -> U3 ----
    denseG(g_Z2, g_U3, g2, be2, W3, &g_stats[2], &g_stats[34], n, sW4);
    gbar();

    // ---- P8: layer-3 gather -> Z3 ----
    gatherG(g_U3, g_Z3, b3, &g_stats[66], &g_stats[98], n, shd);
    gbar();

    // ---- P9: output (4 nodes/warp) ----
    {
        const double* ss = &g_stats[66];
        const double* sq = &g_stats[98];
        double inv = 1.0 / (double)n;
        float4 gl = ((const float4*)g3)[q], bl = ((const float4*)be3)[q];
        float4 fw = ((const float4*)fcW)[q];
        float fb = fcb[0];
        float4 mean, sd;
        double m0 = ss[4*q+0]*inv, m1 = ss[4*q+1]*inv, m2 = ss[4*q+2]*inv, m3 = ss[4*q+3]*inv;
        sd.x = rsqrtf((float)(sq[4*q+0]*inv - m0*m0) + BN_EPS);
        sd.y = rsqrtf((float)(sq[4*q+1]*inv - m1*m1) + BN_EPS);
        sd.z = rsqrtf((float)(sq[4*q+2]*inv - m2*m2) + BN_EPS);
        sd.w = rsqrtf((float)(sq[4*q+3]*inv - m3*m3) + BN_EPS);
        mean.x = (float)m0; mean.y = (float)m1; mean.z = (float)m2; mean.w = (float)m3;
        for (int node = ggrp; node < n; node += NGRP) {
            float4 z = g_Z3[node * 8 + q];
            float4 h;
            h.x = fmaxf(gl.x * ((z.x - mean.x) * sd.x) + bl.x, 0.f);
            h.y = fmaxf(gl.y * ((z.y - mean.y) * sd.y) + bl.y, 0.f);
            h.z = fmaxf(gl.z * ((z.z - mean.z) * sd.z) + bl.z, 0.f);
            h.w = fmaxf(gl.w * ((z.w - mean.w) * sd.w) + bl.w, 0.f);
            float v = h.x * fw.x + h.y * fw.y + h.z * fw.z + h.w * fw.w;
            v += __shfl_xor_sync(gmask, v, 4, 8);
            v += __shfl_xor_sync(gmask, v, 2, 8);
            v += __shfl_xor_sync(gmask, v, 1, 8);
            if (q == 0) out[node] = v + fb;
        }
    }
}

extern "C" void kernel_launch(void* const* d_in, const int* in_sizes, int n_in,
                              void* d_out, int out_size) {
    const float* x   = (const float*)d_in[0];
    const int*   ei  = (const int*)d_in[1];     // int32 edge_index
    const float* W1  = (const float*)d_in[3];
    const float* g1  = (const float*)d_in[5];
    const float* be1 = (const float*)d_in[6];
    const float* W2  = (const float*)d_in[7];
    const float* b2  = (const float*)d_in[8];
    const float* g2  = (const float*)d_in[9];
    const float* be2 = (const float*)d_in[10];
    const float* W3  = (const float*)d_in[11];
    const float* b3  = (const float*)d_in[12];
    const float* g3  = (const float*)d_in[13];
    const float* be3 = (const float*)d_in[14];
    const float* fcW = (const float*)d_in[15];
    const float* fcb = (const float*)d_in[16];
    float* out = (float*)d_out;

    int n = in_sizes[0];
    int E = in_sizes[1] / 2;
    const int* src = ei;
    const int* dst = ei + E;

    k_mega<<<NB, NT>>>(x, src, dst, W1, g1, be1, W2, b2, g2, be2,
                       W3, b3, g3, be3, fcW, fcb, out, n, E);
}